// round 5
// baseline (speedup 1.0000x reference)
#include <cuda_runtime.h>
#include <math.h>

#define N_TOTAL 4096
#define HALF    2048
#define DIM     256
#define EPS     1e-6f
#define MARGIN  0.3f

#define BM 128
#define BN 128
#define BK 16
#define TM 8
#define TN 8

// Scratch (allocation-free): normalized features, squared norms, per-anchor
// hardest-positive (max) and hardest-negative (min) encoded as uint bits.
__device__ float    g_xn[N_TOTAL * DIM];
__device__ float    g_sq[N_TOTAL];
__device__ unsigned g_ap[N_TOTAL];   // init 0          -> max over positives
__device__ unsigned g_an[N_TOTAL];   // init +inf bits  -> min over negatives

// ---------------------------------------------------------------------------
// Kernel 1: row L2-normalize (x / (||x|| + 1e-6)), compute sq = ||xn||^2,
//           and (re)initialize the reduction buffers every launch.
// One warp per row; 256-float row = 2 float4 per lane.
// ---------------------------------------------------------------------------
__global__ void k_normalize(const float* __restrict__ in) {
    int warp = (blockIdx.x * blockDim.x + threadIdx.x) >> 5;
    int lane = threadIdx.x & 31;
    if (warp >= N_TOTAL) return;

    const float4* row = (const float4*)(in + (size_t)warp * DIM);
    float4 v0 = row[lane];
    float4 v1 = row[lane + 32];
    float s = v0.x*v0.x + v0.y*v0.y + v0.z*v0.z + v0.w*v0.w
            + v1.x*v1.x + v1.y*v1.y + v1.z*v1.z + v1.w*v1.w;
    #pragma unroll
    for (int o = 16; o; o >>= 1) s += __shfl_xor_sync(0xffffffffu, s, o);

    float norm = sqrtf(s);
    float inv  = 1.0f / (norm + EPS);

    v0.x *= inv; v0.y *= inv; v0.z *= inv; v0.w *= inv;
    v1.x *= inv; v1.y *= inv; v1.z *= inv; v1.w *= inv;
    float4* out = (float4*)(g_xn + (size_t)warp * DIM);
    out[lane]      = v0;
    out[lane + 32] = v1;

    if (lane == 0) {
        g_sq[warp] = s * inv * inv;      // == sum(xn^2) analytically
        g_ap[warp] = 0u;                 // max identity (matches pos_any=false -> 0)
        g_an[warp] = 0x7F800000u;        // +inf bits (fixed to 1.0 later if untouched)
    }
}

// ---------------------------------------------------------------------------
// Kernel 2: fused 128x128-tile SGEMM (K=256) + distance + masked hard mining.
// Tile (br, bc): rows = first-half anchors [br*128, ...), cols = second-half
// anchors [2048 + bc*128, ...). Each element updates BOTH its row anchor
// (reduce over cols) and its column anchor (reduce over rows).
// 256 threads, 8x8 accumulators per thread.
// ---------------------------------------------------------------------------
__global__ void __launch_bounds__(256) k_mine(const int* __restrict__ tgt) {
    __shared__ float As[BK][BM];
    __shared__ float Bs[BK][BN];
    __shared__ unsigned s_rp[BM], s_rn[BM], s_cp[BN], s_cn[BN];
    __shared__ int   s_lr[BM], s_lc[BN];
    __shared__ float s_sqr[BM], s_sqc[BN];

    const int tid  = threadIdx.x;
    const int br   = blockIdx.y, bc = blockIdx.x;
    const int row0 = br * BM;            // first-half anchor base
    const int col0 = bc * BN;            // second-half local base (global = HALF+col0)

    if (tid < 128) {
        s_rp[tid] = 0u;          s_rn[tid] = 0x7F800000u;
        s_cp[tid] = 0u;          s_cn[tid] = 0x7F800000u;
        s_lr[tid] = tgt[row0 + tid];
        s_lc[tid] = tgt[HALF + col0 + tid];
        s_sqr[tid] = g_sq[row0 + tid];
        s_sqc[tid] = g_sq[HALF + col0 + tid];
    }

    const int tx = tid & 15, ty = tid >> 4;
    const float* A = g_xn + (size_t)row0 * DIM;
    const float* B = g_xn + (size_t)(HALF + col0) * DIM;

    float acc[TM][TN];
    #pragma unroll
    for (int i = 0; i < TM; i++)
        #pragma unroll
        for (int j = 0; j < TN; j++) acc[i][j] = 0.0f;

    for (int k0 = 0; k0 < DIM; k0 += BK) {
        // Load 128x16 A and B tiles (512 float4 each; 2 per thread), transposed
        // into [BK][128] for coalesced compute reads.
        #pragma unroll
        for (int i = 0; i < 2; i++) {
            int idx = tid + i * 256;
            int r   = idx >> 2;
            int c4  = (idx & 3) << 2;
            float4 va = *(const float4*)(A + r * DIM + k0 + c4);
            As[c4+0][r] = va.x; As[c4+1][r] = va.y;
            As[c4+2][r] = va.z; As[c4+3][r] = va.w;
            float4 vb = *(const float4*)(B + r * DIM + k0 + c4);
            Bs[c4+0][r] = vb.x; Bs[c4+1][r] = vb.y;
            Bs[c4+2][r] = vb.z; Bs[c4+3][r] = vb.w;
        }
        __syncthreads();

        #pragma unroll
        for (int k = 0; k < BK; k++) {
            float af[TM], bf[TN];
            #pragma unroll
            for (int i = 0; i < TM; i++) af[i] = As[k][ty * TM + i];
            #pragma unroll
            for (int j = 0; j < TN; j++) bf[j] = Bs[k][tx * TN + j];
            #pragma unroll
            for (int i = 0; i < TM; i++)
                #pragma unroll
                for (int j = 0; j < TN; j++)
                    acc[i][j] = fmaf(af[i], bf[j], acc[i][j]);
        }
        __syncthreads();
    }

    // Epilogue: distance + masked max/min, thread-local first.
    float rp[TM], rn[TM], cp[TN], cn[TN];
    #pragma unroll
    for (int i = 0; i < TM; i++) { rp[i] = 0.0f; rn[i] = INFINITY; }
    #pragma unroll
    for (int j = 0; j < TN; j++) { cp[j] = 0.0f; cn[j] = INFINITY; }

    #pragma unroll
    for (int i = 0; i < TM; i++) {
        int r = ty * TM + i;
        float sr = s_sqr[r];
        int   lr = s_lr[r];
        #pragma unroll
        for (int j = 0; j < TN; j++) {
            int c = tx * TN + j;
            float d = sqrtf(fmaxf(sr + s_sqc[c] - 2.0f * acc[i][j], EPS));
            if (lr == s_lc[c]) {
                rp[i] = fmaxf(rp[i], d);
                cp[j] = fmaxf(cp[j], d);
            } else {
                rn[i] = fminf(rn[i], d);
                cn[j] = fminf(cn[j], d);
            }
        }
    }

    // Combine across threads via shared atomics (uint bit ordering == float
    // ordering for positive values; all distances >= sqrt(1e-6) > 0).
    #pragma unroll
    for (int i = 0; i < TM; i++) {
        int r = ty * TM + i;
        if (rp[i] > 0.0f)     atomicMax(&s_rp[r], __float_as_uint(rp[i]));
        if (rn[i] < INFINITY) atomicMin(&s_rn[r], __float_as_uint(rn[i]));
    }
    #pragma unroll
    for (int j = 0; j < TN; j++) {
        int c = tx * TN + j;
        if (cp[j] > 0.0f)     atomicMax(&s_cp[c], __float_as_uint(cp[j]));
        if (cn[j] < INFINITY) atomicMin(&s_cn[c], __float_as_uint(cn[j]));
    }
    __syncthreads();

    // One global atomic pair per anchor touched by this tile.
    if (tid < 128) {
        atomicMax(&g_ap[row0 + tid], s_rp[tid]);
        atomicMin(&g_an[row0 + tid], s_rn[tid]);
    } else {
        int t = tid - 128;
        atomicMax(&g_ap[HALF + col0 + t], s_cp[t]);
        atomicMin(&g_an[HALF + col0 + t], s_cn[t]);
    }
}

// ---------------------------------------------------------------------------
// Kernel 3: final loss = mean(relu(ap - an + margin)), with an = 1.0 when no
// negative existed (an bits still +inf).
// ---------------------------------------------------------------------------
__global__ void k_loss(float* __restrict__ out) {
    __shared__ float red[256];
    int tid = threadIdx.x;
    float sum = 0.0f;
    for (int i = tid; i < N_TOTAL; i += 256) {
        float    ap  = __uint_as_float(g_ap[i]);
        unsigned anb = g_an[i];
        float    an  = (anb == 0x7F800000u) ? 1.0f : __uint_as_float(anb);
        sum += fmaxf(ap - an + MARGIN, 0.0f);
    }
    red[tid] = sum;
    __syncthreads();
    #pragma unroll
    for (int s = 128; s; s >>= 1) {
        if (tid < s) red[tid] += red[tid + s];
        __syncthreads();
    }
    if (tid == 0) out[0] = red[0] / (float)N_TOTAL;
}

// ---------------------------------------------------------------------------
extern "C" void kernel_launch(void* const* d_in, const int* in_sizes, int n_in,
                              void* d_out, int out_size) {
    const float* inputs  = (const float*)d_in[0];
    const int*   targets = (const int*)d_in[1];
    (void)in_sizes; (void)n_in; (void)out_size;

    k_normalize<<<N_TOTAL / 8, 256>>>(inputs);          // 512 blocks x 8 warps
    dim3 grid(HALF / BN, HALF / BM);                    // 16 x 16 tiles
    k_mine<<<grid, 256>>>(targets);
    k_loss<<<1, 256>>>((float*)d_out);
}

// round 6
// speedup vs baseline: 1.7963x; 1.7963x over previous
#include <cuda_runtime.h>
#include <cuda_bf16.h>
#include <math.h>

#define N_TOTAL 4096
#define HALF    2048
#define DIM     256
#define EPS     1e-6f
#define MARGIN  0.3f

#define BM   128
#define BN   128
#define BK   32          // bf16 elements per k0 block
#define ASTR 40          // padded row stride (bf16) -> 80B, conflict-free ldmatrix

// Scratch (allocation-free)
__device__ __nv_bfloat16 g_hi[N_TOTAL * DIM];
__device__ __nv_bfloat16 g_lo[N_TOTAL * DIM];
__device__ float    g_sq[N_TOTAL];
__device__ unsigned g_ap[N_TOTAL];   // init 0         -> max over positives
__device__ unsigned g_an[N_TOTAL];   // init +inf bits -> min over negatives

static __device__ __forceinline__ unsigned su32(const void* p) {
    return (unsigned)__cvta_generic_to_shared(p);
}

// ---------------------------------------------------------------------------
// Kernel 1: L2-normalize rows, emit bf16 hi/lo split + fp32 squared norm,
// and reinitialize reduction buffers. One warp per row.
// ---------------------------------------------------------------------------
__global__ void k_normalize(const float* __restrict__ in) {
    int warp = (blockIdx.x * blockDim.x + threadIdx.x) >> 5;
    int lane = threadIdx.x & 31;
    if (warp >= N_TOTAL) return;

    const float4* row = (const float4*)(in + (size_t)warp * DIM);
    float4 v0 = row[lane];
    float4 v1 = row[lane + 32];
    float s = v0.x*v0.x + v0.y*v0.y + v0.z*v0.z + v0.w*v0.w
            + v1.x*v1.x + v1.y*v1.y + v1.z*v1.z + v1.w*v1.w;
    #pragma unroll
    for (int o = 16; o; o >>= 1) s += __shfl_xor_sync(0xffffffffu, s, o);

    float inv = 1.0f / (sqrtf(s) + EPS);
    v0.x *= inv; v0.y *= inv; v0.z *= inv; v0.w *= inv;
    v1.x *= inv; v1.y *= inv; v1.z *= inv; v1.w *= inv;

    __nv_bfloat16* H = g_hi + (size_t)warp * DIM;
    __nv_bfloat16* L = g_lo + (size_t)warp * DIM;
    float f[8] = {v0.x, v0.y, v0.z, v0.w, v1.x, v1.y, v1.z, v1.w};
    #pragma unroll
    for (int g = 0; g < 2; g++) {
        int col = 4 * lane + g * 128;
        __nv_bfloat16 h0 = __float2bfloat16(f[g*4+0]);
        __nv_bfloat16 h1 = __float2bfloat16(f[g*4+1]);
        __nv_bfloat16 h2 = __float2bfloat16(f[g*4+2]);
        __nv_bfloat16 h3 = __float2bfloat16(f[g*4+3]);
        __nv_bfloat16 l0 = __float2bfloat16(f[g*4+0] - __bfloat162float(h0));
        __nv_bfloat16 l1 = __float2bfloat16(f[g*4+1] - __bfloat162float(h1));
        __nv_bfloat16 l2 = __float2bfloat16(f[g*4+2] - __bfloat162float(h2));
        __nv_bfloat16 l3 = __float2bfloat16(f[g*4+3] - __bfloat162float(h3));
        *(__nv_bfloat162*)(H + col)     = __nv_bfloat162(h0, h1);
        *(__nv_bfloat162*)(H + col + 2) = __nv_bfloat162(h2, h3);
        *(__nv_bfloat162*)(L + col)     = __nv_bfloat162(l0, l1);
        *(__nv_bfloat162*)(L + col + 2) = __nv_bfloat162(l2, l3);
    }

    if (lane == 0) {
        g_sq[warp] = s * inv * inv;
        g_ap[warp] = 0u;
        g_an[warp] = 0x7F800000u;
    }
}

// ---------------------------------------------------------------------------
// Kernel 2: 128x128 tile GEMM on tensor pipe (mma.sync bf16, 3-term split:
// hi*hi + hi*lo + lo*hi) + fused distance + masked hard mining.
// 256 threads = 8 warps in a 2x4 grid; each warp owns a 64x32 C tile.
// ---------------------------------------------------------------------------
__global__ void __launch_bounds__(256, 2) k_mine(const int* __restrict__ tgt) {
    __shared__ __nv_bfloat16 Ahi[BM * ASTR], Alo[BM * ASTR];
    __shared__ __nv_bfloat16 Bhi[BN * ASTR], Blo[BN * ASTR];
    __shared__ unsigned s_rp[BM], s_rn[BM], s_cp[BN], s_cn[BN];
    __shared__ int   s_lr[BM], s_lc[BN];
    __shared__ float s_sqr[BM], s_sqc[BN];

    const int tid  = threadIdx.x;
    const int br   = blockIdx.y, bc = blockIdx.x;
    const int row0 = br * BM;
    const int col0 = bc * BN;

    if (tid < 128) {
        s_rp[tid] = 0u;          s_rn[tid] = 0x7F800000u;
        s_cp[tid] = 0u;          s_cn[tid] = 0x7F800000u;
        s_lr[tid]  = tgt[row0 + tid];
        s_lc[tid]  = tgt[HALF + col0 + tid];
        s_sqr[tid] = g_sq[row0 + tid];
        s_sqc[tid] = g_sq[HALF + col0 + tid];
    }

    const int lane = tid & 31, w = tid >> 5;
    const int m0 = (w >> 2) * 64;        // warp row base within tile
    const int n0 = (w & 3)  * 32;        // warp col base within tile

    const size_t aoff = (size_t)row0 * DIM;
    const size_t boff = (size_t)(HALF + col0) * DIM;

    float acc[4][4][4];
    #pragma unroll
    for (int mt = 0; mt < 4; mt++)
        #pragma unroll
        for (int nt = 0; nt < 4; nt++)
            #pragma unroll
            for (int q = 0; q < 4; q++) acc[mt][nt][q] = 0.0f;

    // fragment-load lane addressing (element offsets within a tile)
    const int arow = lane & 15;                 // A: rows m0+arow
    const int acolo = (lane >> 4) * 8;          // A: col kk + 0/8
    const int brow = lane & 7;                  // B: rows n0+brow
    const int bcolo = ((lane >> 3) & 1) * 8;    // B: col kk + 0/8

    for (int k0 = 0; k0 < DIM; k0 += BK) {
        __syncthreads();
        // Load hi/lo A and B tiles: 128 rows x 32 bf16 each = 512 uint4/tile,
        // 2 per thread per tile.
        #pragma unroll
        for (int i = 0; i < 2; i++) {
            int idx = tid + i * 256;
            int r   = idx >> 2;
            int c8  = (idx & 3) << 3;
            size_t ga = aoff + (size_t)r * DIM + k0 + c8;
            size_t gb = boff + (size_t)r * DIM + k0 + c8;
            *(uint4*)&Ahi[r * ASTR + c8] = *(const uint4*)(g_hi + ga);
            *(uint4*)&Alo[r * ASTR + c8] = *(const uint4*)(g_lo + ga);
            *(uint4*)&Bhi[r * ASTR + c8] = *(const uint4*)(g_hi + gb);
            *(uint4*)&Blo[r * ASTR + c8] = *(const uint4*)(g_lo + gb);
        }
        __syncthreads();

        #pragma unroll
        for (int seg = 0; seg < 3; seg++) {
            const __nv_bfloat16* As = (seg == 2) ? Alo : Ahi;
            const __nv_bfloat16* Bs = (seg == 1) ? Blo : Bhi;
            #pragma unroll
            for (int kk = 0; kk < BK; kk += 16) {
                unsigned a[4][4], b[4][2];
                #pragma unroll
                for (int mt = 0; mt < 4; mt++) {
                    unsigned ad = su32(&As[(m0 + mt * 16 + arow) * ASTR + kk + acolo]);
                    asm volatile(
                        "ldmatrix.sync.aligned.m8n8.x4.shared.b16 {%0,%1,%2,%3}, [%4];"
                        : "=r"(a[mt][0]), "=r"(a[mt][1]), "=r"(a[mt][2]), "=r"(a[mt][3])
                        : "r"(ad));
                }
                #pragma unroll
                for (int nt = 0; nt < 4; nt++) {
                    unsigned bd = su32(&Bs[(n0 + nt * 8 + brow) * ASTR + kk + bcolo]);
                    asm volatile(
                        "ldmatrix.sync.aligned.m8n8.x2.shared.b16 {%0,%1}, [%2];"
                        : "=r"(b[nt][0]), "=r"(b[nt][1])
                        : "r"(bd));
                }
                #pragma unroll
                for (int mt = 0; mt < 4; mt++)
                    #pragma unroll
                    for (int nt = 0; nt < 4; nt++) {
                        asm volatile(
                            "mma.sync.aligned.m16n8k16.row.col.f32.bf16.bf16.f32 "
                            "{%0,%1,%2,%3}, {%4,%5,%6,%7}, {%8,%9}, {%0,%1,%2,%3};"
                            : "+f"(acc[mt][nt][0]), "+f"(acc[mt][nt][1]),
                              "+f"(acc[mt][nt][2]), "+f"(acc[mt][nt][3])
                            : "r"(a[mt][0]), "r"(a[mt][1]), "r"(a[mt][2]), "r"(a[mt][3]),
                              "r"(b[nt][0]), "r"(b[nt][1]));
                    }
            }
        }
    }

    // Epilogue: distance + masked hard mining.
    // C frag mapping (m16n8): reg q = h*2 + c, row = base + h*8 + lane/4,
    // col = base + 2*(lane%4) + c.
    float lrp[8], lrn[8], lcp[8], lcn[8];
    #pragma unroll
    for (int i = 0; i < 8; i++) { lrp[i] = 0.0f; lrn[i] = INFINITY;
                                  lcp[i] = 0.0f; lcn[i] = INFINITY; }

    #pragma unroll
    for (int mt = 0; mt < 4; mt++) {
        #pragma unroll
        for (int h = 0; h < 2; h++) {
            int r = m0 + mt * 16 + h * 8 + (lane >> 2);
            float sr = s_sqr[r];
            int   lr = s_lr[r];
            #pragma unroll
            for (int nt = 0; nt < 4; nt++) {
                #pragma unroll
                for (int q = 0; q < 2; q++) {
                    int c = n0 + nt * 8 + ((lane & 3) << 1) + q;
                    float dot = acc[mt][nt][h * 2 + q];
                    float d = sqrtf(fmaxf(sr + s_sqc[c] - 2.0f * dot, EPS));
                    int ri = mt * 2 + h, ci = nt * 2 + q;
                    if (lr == s_lc[c]) {
                        lrp[ri] = fmaxf(lrp[ri], d);
                        lcp[ci] = fmaxf(lcp[ci], d);
                    } else {
                        lrn[ri] = fminf(lrn[ri], d);
                        lcn[ci] = fminf(lcn[ci], d);
                    }
                }
            }
        }
    }

    #pragma unroll
    for (int i = 0; i < 8; i++) {
        int r = m0 + (i >> 1) * 16 + (i & 1) * 8 + (lane >> 2);
        if (lrp[i] > 0.0f)     atomicMax(&s_rp[r], __float_as_uint(lrp[i]));
        if (lrn[i] < INFINITY) atomicMin(&s_rn[r], __float_as_uint(lrn[i]));
    }
    #pragma unroll
    for (int j = 0; j < 8; j++) {
        int c = n0 + (j >> 1) * 8 + ((lane & 3) << 1) + (j & 1);
        if (lcp[j] > 0.0f)     atomicMax(&s_cp[c], __float_as_uint(lcp[j]));
        if (lcn[j] < INFINITY) atomicMin(&s_cn[c], __float_as_uint(lcn[j]));
    }
    __syncthreads();

    if (tid < 128) {
        atomicMax(&g_ap[row0 + tid], s_rp[tid]);
        atomicMin(&g_an[row0 + tid], s_rn[tid]);
    } else {
        int t = tid - 128;
        atomicMax(&g_ap[HALF + col0 + t], s_cp[t]);
        atomicMin(&g_an[HALF + col0 + t], s_cn[t]);
    }
}

// ---------------------------------------------------------------------------
// Kernel 3: loss = mean(relu(ap - an + margin)); an defaults to 1.0 if no
// negative was ever seen (bits still +inf).
// ---------------------------------------------------------------------------
__global__ void k_loss(float* __restrict__ out) {
    __shared__ float red[256];
    int tid = threadIdx.x;
    float sum = 0.0f;
    for (int i = tid; i < N_TOTAL; i += 256) {
        float    ap  = __uint_as_float(g_ap[i]);
        unsigned anb = g_an[i];
        float    an  = (anb == 0x7F800000u) ? 1.0f : __uint_as_float(anb);
        sum += fmaxf(ap - an + MARGIN, 0.0f);
    }
    red[tid] = sum;
    __syncthreads();
    #pragma unroll
    for (int s = 128; s; s >>= 1) {
        if (tid < s) red[tid] += red[tid + s];
        __syncthreads();
    }
    if (tid == 0) out[0] = red[0] / (float)N_TOTAL;
}

// ---------------------------------------------------------------------------
extern "C" void kernel_launch(void* const* d_in, const int* in_sizes, int n_in,
                              void* d_out, int out_size) {
    const float* inputs  = (const float*)d_in[0];
    const int*   targets = (const int*)d_in[1];
    (void)in_sizes; (void)n_in; (void)out_size;

    k_normalize<<<N_TOTAL / 8, 256>>>(inputs);
    dim3 grid(HALF / BN, HALF / BM);          // 16 x 16 tiles
    k_mine<<<grid, 256>>>(targets);
    k_loss<<<1, 256>>>((float*)d_out);
}

// round 9
// speedup vs baseline: 3.0632x; 1.7053x over previous
#include <cuda_runtime.h>
#include <cuda_fp16.h>
#include <math.h>
#include <cstdint>

#define N_TOTAL 4096
#define HALF    2048
#define DIM     256
#define EPS     1e-6f
#define MARGIN  0.3f

#define BM   128
#define BN   128
#define KBLK 32                 // fp16 k-elements per block
#define NKB  (DIM / KBLK)       // 8 k-blocks
#define ROWB 80                 // smem row stride bytes (64B data + 16B pad, conflict-free)
#define TILEB (BM * ROWB)       // 10240 B per tile

// Scratch (allocation-free)
__device__ __half   g_h[N_TOTAL * DIM];
__device__ float    g_sq[N_TOTAL];
__device__ unsigned g_ap[N_TOTAL];   // d^2 max over positives (bits), init 0
__device__ unsigned g_an[N_TOTAL];   // d^2 min over negatives (bits), init +inf

static __device__ __forceinline__ unsigned su32(const void* p) {
    return (unsigned)__cvta_generic_to_shared(p);
}

// ---------------------------------------------------------------------------
// Kernel 1: L2-normalize rows -> fp16 + fp32 squared norm; reinit buffers.
// One warp per row.
// ---------------------------------------------------------------------------
__global__ void k_normalize(const float* __restrict__ in) {
    int warp = (blockIdx.x * blockDim.x + threadIdx.x) >> 5;
    int lane = threadIdx.x & 31;
    if (warp >= N_TOTAL) return;

    const float4* row = (const float4*)(in + (size_t)warp * DIM);
    float4 v0 = row[lane];
    float4 v1 = row[lane + 32];
    float s = v0.x*v0.x + v0.y*v0.y + v0.z*v0.z + v0.w*v0.w
            + v1.x*v1.x + v1.y*v1.y + v1.z*v1.z + v1.w*v1.w;
    #pragma unroll
    for (int o = 16; o; o >>= 1) s += __shfl_xor_sync(0xffffffffu, s, o);

    float inv = 1.0f / (sqrtf(s) + EPS);

    __half2 h0 = __floats2half2_rn(v0.x * inv, v0.y * inv);
    __half2 h1 = __floats2half2_rn(v0.z * inv, v0.w * inv);
    __half2 h2 = __floats2half2_rn(v1.x * inv, v1.y * inv);
    __half2 h3 = __floats2half2_rn(v1.z * inv, v1.w * inv);

    __half* H = g_h + (size_t)warp * DIM;
    *(__half2*)(H + 4 * lane)           = h0;
    *(__half2*)(H + 4 * lane + 2)       = h1;
    *(__half2*)(H + 128 + 4 * lane)     = h2;
    *(__half2*)(H + 128 + 4 * lane + 2) = h3;

    if (lane == 0) {
        g_sq[warp] = s * inv * inv;
        g_ap[warp] = 0u;
        g_an[warp] = 0x7F800000u;
    }
}

// ---------------------------------------------------------------------------
// Kernel 2: fp16 mma.sync 128x128 GEMM, cp.async double-buffered k-blocks,
// fused SQUARED-distance hard mining (sqrt deferred to k_loss).
// 256 threads = 8 warps (2x4); warp tile 64x32.
// ---------------------------------------------------------------------------
__global__ void __launch_bounds__(256, 2) k_mine(const int* __restrict__ tgt) {
    __shared__ __align__(128) char tA[2][TILEB];
    __shared__ __align__(128) char tB[2][TILEB];
    __shared__ unsigned s_rp[BM], s_rn[BM], s_cp[BN], s_cn[BN];
    __shared__ int   s_lr[BM], s_lc[BN];
    __shared__ float s_sqr[BM], s_sqc[BN];

    const int tid  = threadIdx.x, lane = tid & 31, w = tid >> 5;
    const int row0 = blockIdx.y * BM;
    const int col0 = blockIdx.x * BN;

    if (tid < 128) {
        s_rp[tid] = 0u;          s_rn[tid] = 0x7F800000u;
        s_cp[tid] = 0u;          s_cn[tid] = 0x7F800000u;
        s_lr[tid]  = tgt[row0 + tid];
        s_lc[tid]  = tgt[HALF + col0 + tid];
        s_sqr[tid] = g_sq[row0 + tid];
        s_sqc[tid] = g_sq[HALF + col0 + tid];
    }

    const __half* Ag = g_h + (size_t)row0 * DIM;
    const __half* Bg = g_h + (size_t)(HALF + col0) * DIM;

    // cp.async one k-block into buffer `buf`: per tile 128 rows x 4 x 16B chunks.
    auto prefetch = [&](int kb, int buf) {
        #pragma unroll
        for (int i = 0; i < 4; i++) {
            int id  = tid + i * 256;          // 0..1023
            int idx = id & 511;
            int r   = idx >> 2, c = idx & 3;  // row, 16B chunk
            const __half* src = ((id >> 9) ? Bg : Ag)
                              + (size_t)r * DIM + kb * KBLK + c * 8;
            unsigned dst = su32((id >> 9) ? &tB[buf][0] : &tA[buf][0])
                         + (unsigned)(r * ROWB + c * 16);
            asm volatile("cp.async.cg.shared.global [%0], [%1], 16;"
                         :: "r"(dst), "l"(src));
        }
    };

    prefetch(0, 0);
    asm volatile("cp.async.commit_group;" ::: "memory");

    const int m0 = (w >> 2) * 64;
    const int n0 = (w & 3)  * 32;
    const unsigned aoff = (unsigned)((lane & 15) * ROWB + (lane >> 4) * 16);
    const unsigned boff = (unsigned)((lane & 7)  * ROWB + ((lane >> 3) & 1) * 16);

    float acc[4][4][4];
    #pragma unroll
    for (int mt = 0; mt < 4; mt++)
        #pragma unroll
        for (int nt = 0; nt < 4; nt++)
            #pragma unroll
            for (int q = 0; q < 4; q++) acc[mt][nt][q] = 0.0f;

    for (int kb = 0; kb < NKB; kb++) {
        if (kb + 1 < NKB) {
            prefetch(kb + 1, (kb + 1) & 1);
            asm volatile("cp.async.commit_group;" ::: "memory");
            asm volatile("cp.async.wait_group 1;" ::: "memory");
        } else {
            asm volatile("cp.async.wait_group 0;" ::: "memory");
        }
        __syncthreads();

        const unsigned aT = su32(&tA[kb & 1][0]);
        const unsigned bT = su32(&tB[kb & 1][0]);
        #pragma unroll
        for (int kk = 0; kk < 2; kk++) {          // two K=16 steps per block
            unsigned a[4][4], b[4][2];
            #pragma unroll
            for (int mt = 0; mt < 4; mt++) {
                unsigned ad = aT + (unsigned)((m0 + mt * 16) * ROWB + kk * 32) + aoff;
                asm volatile(
                    "ldmatrix.sync.aligned.m8n8.x4.shared.b16 {%0,%1,%2,%3}, [%4];"
                    : "=r"(a[mt][0]), "=r"(a[mt][1]), "=r"(a[mt][2]), "=r"(a[mt][3])
                    : "r"(ad));
            }
            #pragma unroll
            for (int nt = 0; nt < 4; nt++) {
                unsigned bd = bT + (unsigned)((n0 + nt * 8) * ROWB + kk * 32) + boff;
                asm volatile(
                    "ldmatrix.sync.aligned.m8n8.x2.shared.b16 {%0,%1}, [%2];"
                    : "=r"(b[nt][0]), "=r"(b[nt][1])
                    : "r"(bd));
            }
            #pragma unroll
            for (int mt = 0; mt < 4; mt++)
                #pragma unroll
                for (int nt = 0; nt < 4; nt++) {
                    asm volatile(
                        "mma.sync.aligned.m16n8k16.row.col.f32.f16.f16.f32 "
                        "{%0,%1,%2,%3}, {%4,%5,%6,%7}, {%8,%9}, {%0,%1,%2,%3};"
                        : "+f"(acc[mt][nt][0]), "+f"(acc[mt][nt][1]),
                          "+f"(acc[mt][nt][2]), "+f"(acc[mt][nt][3])
                        : "r"(a[mt][0]), "r"(a[mt][1]), "r"(a[mt][2]), "r"(a[mt][3]),
                          "r"(b[nt][0]), "r"(b[nt][1]));
                }
        }
        __syncthreads();
    }

    // Epilogue: SQUARED distance + masked hard mining (sqrt commutes with max/min).
    float lrp[8], lrn[8], lcp[8], lcn[8];
    #pragma unroll
    for (int i = 0; i < 8; i++) { lrp[i] = 0.0f; lrn[i] = INFINITY;
                                  lcp[i] = 0.0f; lcn[i] = INFINITY; }

    #pragma unroll
    for (int mt = 0; mt < 4; mt++) {
        #pragma unroll
        for (int h = 0; h < 2; h++) {
            int r = m0 + mt * 16 + h * 8 + (lane >> 2);
            float sr = s_sqr[r];
            int   lr = s_lr[r];
            #pragma unroll
            for (int nt = 0; nt < 4; nt++) {
                #pragma unroll
                for (int q = 0; q < 2; q++) {
                    int c = n0 + nt * 8 + ((lane & 3) << 1) + q;
                    float dot = acc[mt][nt][h * 2 + q];
                    float d2  = fmaxf(fmaf(-2.0f, dot, sr + s_sqc[c]), EPS);
                    int ri = mt * 2 + h, ci = nt * 2 + q;
                    if (lr == s_lc[c]) {
                        lrp[ri] = fmaxf(lrp[ri], d2);
                        lcp[ci] = fmaxf(lcp[ci], d2);
                    } else {
                        lrn[ri] = fminf(lrn[ri], d2);
                        lcn[ci] = fminf(lcn[ci], d2);
                    }
                }
            }
        }
    }

    #pragma unroll
    for (int i = 0; i < 8; i++) {
        int r = m0 + (i >> 1) * 16 + (i & 1) * 8 + (lane >> 2);
        if (lrp[i] > 0.0f)     atomicMax(&s_rp[r], __float_as_uint(lrp[i]));
        if (lrn[i] < INFINITY) atomicMin(&s_rn[r], __float_as_uint(lrn[i]));
    }
    #pragma unroll
    for (int j = 0; j < 8; j++) {
        int c = n0 + (j >> 1) * 8 + ((lane & 3) << 1) + (j & 1);
        if (lcp[j] > 0.0f)     atomicMax(&s_cp[c], __float_as_uint(lcp[j]));
        if (lcn[j] < INFINITY) atomicMin(&s_cn[c], __float_as_uint(lcn[j]));
    }
    __syncthreads();

    if (tid < 128) {
        atomicMax(&g_ap[row0 + tid], s_rp[tid]);
        atomicMin(&g_an[row0 + tid], s_rn[tid]);
    } else {
        int t = tid - 128;
        atomicMax(&g_ap[HALF + col0 + t], s_cp[t]);
        atomicMin(&g_an[HALF + col0 + t], s_cn[t]);
    }
}

// ---------------------------------------------------------------------------
// Kernel 3: loss = mean(relu(sqrt(ap2) - an + margin)); an = 1.0 when no
// negative seen (bits still +inf). ap2 = 0 when no positive -> sqrt(0) = 0.
// ---------------------------------------------------------------------------
__global__ void k_loss(float* __restrict__ out) {
    __shared__ float red[256];
    int tid = threadIdx.x;
    float sum = 0.0f;
    for (int i = tid; i < N_TOTAL; i += 256) {
        float ap = sqrtf(__uint_as_float(g_ap[i]));
        unsigned anb = g_an[i];
        float an = (anb == 0x7F800000u) ? 1.0f : sqrtf(__uint_as_float(anb));
        sum += fmaxf(ap - an + MARGIN, 0.0f);
    }
    red[tid] = sum;
    __syncthreads();
    #pragma unroll
    for (int s = 128; s; s >>= 1) {
        if (tid < s) red[tid] += red[tid + s];
        __syncthreads();
    }
    if (tid == 0) out[0] = red[0] / (float)N_TOTAL;
}

// ---------------------------------------------------------------------------
extern "C" void kernel_launch(void* const* d_in, const int* in_sizes, int n_in,
                              void* d_out, int out_size) {
    const float* inputs  = (const float*)d_in[0];
    const int*   targets = (const int*)d_in[1];
    (void)in_sizes; (void)n_in; (void)out_size;

    k_normalize<<<N_TOTAL / 8, 256>>>(inputs);
    dim3 grid(HALF / BN, HALF / BM);          // 16 x 16 tiles, single wave @ occ 2
    k_mine<<<grid, 256>>>(targets);
    k_loss<<<1, 256>>>((float*)d_out);
}